// round 16
// baseline (speedup 1.0000x reference)
#include <cuda_runtime.h>
#include <cstdint>

// y[t,b,f] = sum_{k=0..20} x[t+k,b,f] * w[f,k], zero-padded past t=T-1.
// Thread owns two adjacent features (one float2 column) and a 64-long time
// strip: 16 fully-unrolled chunks of 4 with a 20-element carried register
// window.
//
// KEY CHANGE: weights live in PRIVATE smem (same thread writes & reads -> no
// barriers/conflicts) and are consumed in register batches of 7: one 7-wide
// LDS.64 burst (ILP=7, 29-cyc latency amortized over 28 FMA2s) per k-batch,
// k-batch-outer x 4 accumulators inner. Live regs drop to ~80 => 3 CTAs/SM
// (24 warps) under __launch_bounds__(256,3) — breaking the 128-reg / 2-CTA
// wall that pinned every previous variant at DRAM~60%. Fresh loads are only
// touched in the last k-batch, so 2/3 of each chunk's FMAs cover them.

#define FMA_F32X2(d, a, b, c) \
    asm("fma.rn.f32x2 %0, %1, %2, %3;" : "=l"(d) : "l"(a), "l"(b), "l"(c))
#define MUL_F32X2(d, a, b) \
    asm("mul.rn.f32x2 %0, %1, %2;" : "=l"(d) : "l"(a), "l"(b))

namespace la {
constexpr int T = 2048;
constexpr int B = 16;
constexpr int F = 1024;
constexpr int CTX = 20;
constexpr int K = 21;                  // CTX + 1 taps
constexpr int KB = 7;                  // taps per weight batch
constexpr int NKB = K / KB;            // 3 batches
constexpr int BF2 = (B * F) / 2;       // timestep stride in float2 units = 8192
constexpr int TCHUNK = 64;             // t's per thread
constexpr int STEP = 4;                // t's per inner chunk (low reg pressure)
constexpr int NCHUNK = TCHUNK / STEP;  // 16, fully unrolled
constexpr int NTHR = 256;
}  // namespace la

__global__ void __launch_bounds__(256, 3)
lookahead_kernel(const unsigned long long* __restrict__ x2,  // x as float2 (u64 bits)
                 const float* __restrict__ w,
                 unsigned long long* __restrict__ y2)
{
    using namespace la;
    // Private per-thread weight store: sw[k*NTHR + tid]. 21*256*8 = 43008 B.
    __shared__ unsigned long long sw[K * NTHR];

    const int tid   = threadIdx.x;
    const int fpair = blockIdx.x * blockDim.x + tid;          // 0..511
    const int b     = blockIdx.y;                             // 0..15
    const int t0    = blockIdx.z * TCHUNK;                    // 0,64,...,1984
    const int f0    = fpair * 2;

    // Stage packed weight pairs (lo = f0, hi = f0+1) into smem, one-time.
#pragma unroll
    for (int k = 0; k < K; k++) {
        const unsigned int lo = __float_as_uint(__ldg(&w[(size_t)f0 * K + k]));
        const unsigned int hi = __float_as_uint(__ldg(&w[(size_t)(f0 + 1) * K + k]));
        sw[k * NTHR + tid] = (unsigned long long)lo | ((unsigned long long)hi << 32);
    }

    const unsigned long long* __restrict__ xp = x2 + (size_t)b * (F / 2) + fpair;
    unsigned long long* __restrict__       yp = y2 + (size_t)b * (F / 2) + fpair;

    // win[0..19]: carried window; win[20..23]: fresh loads for this chunk.
    unsigned long long win[STEP + CTX];

    // Preload first CTX timesteps (t0+19 <= 2003 < T: always in-bounds).
#pragma unroll
    for (int i = 0; i < CTX; i++)
        win[i] = __ldg(&xp[(size_t)(t0 + i) * BF2]);

#pragma unroll
    for (int c = 0; c < NCHUNK; c++) {
        const int tb = t0 + c * STEP;

        // Fresh loads for this chunk — consumed only in the LAST k-batch
        // below (~56 FMA2s later per warp, x6 warps/SMSP of wall-clock).
#pragma unroll
        for (int i = 0; i < STEP; i++) {
            const int t = tb + CTX + i;
            win[CTX + i] = (t < T) ? __ldg(&xp[(size_t)t * BF2]) : 0ULL;
        }

        unsigned long long acc[STEP];

        // k-batches of 7: burst-load 7 weights (ILP=7 LDS), then 28 FMA2s.
#pragma unroll
        for (int kb = 0; kb < NKB; kb++) {
            unsigned long long wb[KB];
#pragma unroll
            for (int j = 0; j < KB; j++)
                wb[j] = sw[(kb * KB + j) * NTHR + tid];

#pragma unroll
            for (int j = 0; j < KB; j++) {
                const int k = kb * KB + j;
#pragma unroll
                for (int i = 0; i < STEP; i++) {
                    if (k == 0)
                        MUL_F32X2(acc[i], win[i], wb[j]);
                    else
                        FMA_F32X2(acc[i], win[i + k], wb[j], acc[i]);
                }
            }
        }

        // Streaming stores: keep L2 for the read stream.
#pragma unroll
        for (int i = 0; i < STEP; i++)
            __stcs(&yp[(size_t)(tb + i) * BF2], acc[i]);

        // Rotate carried window — renaming under full unroll.
#pragma unroll
        for (int i = 0; i < CTX; i++)
            win[i] = win[STEP + i];
    }
}

extern "C" void kernel_launch(void* const* d_in, const int* in_sizes, int n_in,
                              void* d_out, int out_size)
{
    using namespace la;
    (void)in_sizes; (void)n_in; (void)out_size;
    const unsigned long long* x2 = (const unsigned long long*)d_in[0];  // x: (T,B,F) f32
    const float*              w  = (const float*)d_in[1];               // weight: (F,21) f32
    // d_in[2] = tail_padding (int, ==1): baked into the zero-fill guard.
    unsigned long long* y2 = (unsigned long long*)d_out;                // y: (T,B,F) f32

    dim3 block(NTHR, 1, 1);
    dim3 grid((F / 2) / NTHR, B, T / TCHUNK);  // (2, 16, 32) = 1024 blocks
    lookahead_kernel<<<grid, block>>>(x2, w, y2);
}

// round 17
// speedup vs baseline: 1.8326x; 1.8326x over previous
#include <cuda_runtime.h>
#include <cstdint>

// y[t,b,f] = sum_{k=0..20} x[t+k,b,f] * w[f,k], zero-padded past t=T-1.
//
// Barrier-staged cp.async pipeline with a circular smem time-ring:
//  - CTA owns a panel of 64 fpairs (128 features) x 1024 timesteps for one b.
//  - x streams through a 4-stage x 32-timestep circular ring in dynamic smem;
//    each element is fetched from DRAM exactly ONCE (read amp 33/32 = 1.03).
//  - Producers: cp.async.cg 16B with zfill for the tail — registerless and
//    scoreboardless; two full stages (32KB/CTA) always in flight, so DRAM
//    latency is hidden structurally, not by occupancy.
//  - Consumers: per-thread 8-output strip, 8-reg rolling window fed by
//    conflict-free LDS.64 (28 loads / 8 outputs); weights in registers;
//    dense 168-FMA2 blocks (the schedule R2/R15 proved out).
// Packed fma.rn.f32x2 halves fp32 work; streaming stores protect L2.

#define FMA_F32X2(d, a, b, c) \
    asm("fma.rn.f32x2 %0, %1, %2, %3;" : "=l"(d) : "l"(a), "l"(b), "l"(c))
#define MUL_F32X2(d, a, b) \
    asm("mul.rn.f32x2 %0, %1, %2;" : "=l"(d) : "l"(a), "l"(b))
#define CP_ASYNC_16_ZFILL(dst, src, n) \
    asm volatile("cp.async.cg.shared.global [%0], [%1], 16, %2;" \
                 :: "r"(dst), "l"(src), "r"(n))
#define CP_COMMIT() asm volatile("cp.async.commit_group;" ::: "memory")
#define CP_WAIT_2() asm volatile("cp.async.wait_group 2;" ::: "memory")

namespace la {
constexpr int T   = 2048;
constexpr int B   = 16;
constexpr int F   = 1024;
constexpr int CTX = 20;
constexpr int K   = 21;                 // taps
constexpr int BF2 = (B * F) / 2;        // u64 per timestep = 8192
constexpr int FF  = 64;                 // fpairs per CTA
constexpr int TT  = 32;                 // timesteps per stage
constexpr int NST = 4;                  // ring stages
constexpr int RING = NST * TT;          // 128 timesteps resident
constexpr int TCTA = 1024;              // timesteps per CTA (TSPLIT=2)
constexpr int NSTG = TCTA / TT;         // 32 compute stages
constexpr int NTHR = 256;
constexpr int SMEM_BYTES = RING * FF * 8;  // 65536
}  // namespace la

__global__ void __launch_bounds__(256, 2)
lookahead_kernel(const unsigned long long* __restrict__ x2,  // x as float2 (u64 bits)
                 const float* __restrict__ w,
                 unsigned long long* __restrict__ y2)
{
    using namespace la;
    extern __shared__ unsigned long long ring[];  // [RING][FF]

    const int tid   = threadIdx.x;
    const int fb    = blockIdx.x;          // 0..7   feature block
    const int b     = blockIdx.y;          // 0..15
    const int t0    = blockIdx.z * TCTA;   // 0 or 1024
    const int fp    = tid & (FF - 1);      // fpair within block
    const int strip = tid >> 6;            // 0..3 -> 8-ts strip within stage
    const int f0    = (fb * FF + fp) * 2;

    // Weights in registers (R14/R16 proved smem weights serialize the taps).
    unsigned long long wk[K];
#pragma unroll
    for (int k = 0; k < K; k++) {
        const unsigned int lo = __float_as_uint(__ldg(&w[(size_t)f0 * K + k]));
        const unsigned int hi = __float_as_uint(__ldg(&w[(size_t)(f0 + 1) * K + k]));
        wk[k] = (unsigned long long)lo | ((unsigned long long)hi << 32);
    }

    // Global panel bases (u64 units).
    const unsigned long long* __restrict__ xg =
        x2 + (size_t)b * (F / 2) + (size_t)fb * FF;
    unsigned long long* __restrict__ yg =
        y2 + (size_t)b * (F / 2) + (size_t)fb * FF + fp;

    const unsigned int rbase = (unsigned int)__cvta_generic_to_shared(ring);

    // Producer: stage s = 32 rows x 512B; thread does 4 x 16B chunks.
    const int prow0 = tid >> 5;        // base row 0..7
    const int pcol  = (tid & 31) * 2;  // u64 col (16B chunk)
    auto load_stage = [&](int s) {
        const int slot = s & (NST - 1);
#pragma unroll
        for (int j = 0; j < 4; j++) {
            const int r  = prow0 + j * 8;          // 0..31
            const int tg = t0 + s * TT + r;        // global timestep
            const unsigned long long* src =
                xg + (size_t)(tg < T ? tg : (T - 1)) * BF2 + pcol;
            const unsigned int n   = (tg < T) ? 16u : 0u;  // zfill tail
            const unsigned int dst =
                rbase + (unsigned int)(((slot * TT + r) * FF + pcol) * 8);
            CP_ASYNC_16_ZFILL(dst, src, n);
        }
    };

    // Prologue: stages 0..2 in flight.
    load_stage(0); CP_COMMIT();
    load_stage(1); CP_COMMIT();
    load_stage(2); CP_COMMIT();

    for (int c = 0; c < NSTG; c++) {
        // Keep 2 stages ahead (stage NSTG covers the 20-ts lookahead;
        // beyond that commit empty groups to keep wait counts uniform).
        if (c + 3 <= NSTG) load_stage(c + 3);
        CP_COMMIT();
        CP_WAIT_2();          // stages <= c+1 complete (per thread)
        __syncthreads();      // make them visible block-wide

        // Compute this thread's 8-output strip from the smem ring.
        const int tb = c * TT + strip * 8;  // CTA-relative first output ts

        unsigned long long xw[8];
#pragma unroll
        for (int i = 0; i < 8; i++)
            xw[i] = ring[((tb + i) & (RING - 1)) * FF + fp];

        unsigned long long acc[8];
#pragma unroll
        for (int i = 0; i < 8; i++)
            MUL_F32X2(acc[i], xw[i], wk[0]);

#pragma unroll
        for (int k = 1; k < K; k++) {
            // Shift rolling window, pull one new timestep from the ring.
#pragma unroll
            for (int i = 0; i < 7; i++) xw[i] = xw[i + 1];
            xw[7] = ring[((tb + k + 7) & (RING - 1)) * FF + fp];
#pragma unroll
            for (int i = 0; i < 8; i++)
                FMA_F32X2(acc[i], xw[i], wk[k], acc[i]);
        }

#pragma unroll
        for (int i = 0; i < 8; i++)
            __stcs(&yg[(size_t)(t0 + tb + i) * BF2], acc[i]);

        __syncthreads();  // strip reads done before slot (c+3)&3 is rewritten
    }
}

extern "C" void kernel_launch(void* const* d_in, const int* in_sizes, int n_in,
                              void* d_out, int out_size)
{
    using namespace la;
    (void)in_sizes; (void)n_in; (void)out_size;
    const unsigned long long* x2 = (const unsigned long long*)d_in[0];  // x: (T,B,F) f32
    const float*              w  = (const float*)d_in[1];               // weight: (F,21) f32
    // d_in[2] = tail_padding (int, ==1): baked into the zfill guard.
    unsigned long long* y2 = (unsigned long long*)d_out;                // y: (T,B,F) f32

    static bool attr_set = false;
    if (!attr_set) {
        cudaFuncSetAttribute(lookahead_kernel,
                             cudaFuncAttributeMaxDynamicSharedMemorySize,
                             SMEM_BYTES);
        attr_set = true;
    }

    dim3 block(NTHR, 1, 1);
    dim3 grid((F / 2) / FF, B, T / TCTA);  // (8, 16, 2) = 256 CTAs
    lookahead_kernel<<<grid, block, SMEM_BYTES>>>(x2, w, y2);
}